// round 12
// baseline (speedup 1.0000x reference)
#include <cuda_runtime.h>
#include <math.h>
#include <stdint.h>

// LiquidNNSensorModel: 2-layer CfC RNN, B=256, T=1024, S=8, H=256.
// R12: warp-autonomous pipeline. 16 groups x 8 ranks, SMEM-resident recurrent
// weights, L2 exchange. Only 2 block syncs per step (pre-epilogue reduction
// fences); barrier waits + h reloads are per-warp (lane0 acquire-spin +
// __syncwarp + warp-local 2KB segment reload). Arrivals: per-warp
// syncwarp + lane0 red.add.release (64/group/phase). LN computed one step
// ahead into a double buffer. h0 double-buffered.

#define NB 256
#define NT 1024
#define NS 8
#define NH 256
#define NG 16        // groups
#define CSZ 8        // CTAs (ranks) per group
#define GB 16        // batches per group
#define NCTA 128
#define NTHR 256

typedef unsigned long long ull;

// ---- global scratch ----
__device__ float4 g_WA0[CSZ * 64 * 32];   // [rank][kq][ol] gh_w0 quads
__device__ float4 g_WA1[CSZ * 64 * 32];   // bb_w0 h-part
__device__ float4 g_WH0[CSZ * 64 * 32];   // gh_w1
__device__ float4 g_WH1[CSZ * 64 * 32];   // bb_w1 h-part
__device__ float4 g_WX1g[CSZ * 64 * 32];  // gx_w1
__device__ float4 g_WX1b[CSZ * 64 * 32];  // bb_w1 x-part
__device__ float2 g_wx0[CSZ * 8 * 32];    // [rank][k][ol] (gx_w0, bb_w0_x)
__device__ float  g_bias[6 * NH];
__device__ float  g_dtT[NT * NB];         // [t][b]
__device__ float  g_h0x[NG * NH * GB];    // exchange: [grp][k][b]
__device__ float  g_h1x[NG * NH * GB];
__device__ unsigned g_bar[NG];

// ---------------------------------------------------------------------------
__global__ void prep_kernel(
    const float* __restrict__ ts,
    const float* __restrict__ bb_w0, const float* __restrict__ gx_w0,
    const float* __restrict__ gx_b0, const float* __restrict__ gh_w0,
    const float* __restrict__ gb0,   const float* __restrict__ lt0,
    const float* __restrict__ bb_w1, const float* __restrict__ gx_w1,
    const float* __restrict__ gx_b1, const float* __restrict__ gh_w1,
    const float* __restrict__ gb1,   const float* __restrict__ lt1,
    const float* __restrict__ bb_b0, const float* __restrict__ bb_b1)
{
    const int tid = threadIdx.x;
    const int i = blockIdx.x * blockDim.x + tid;
    {   // dt transpose
        const int b = i >> 10, t = i & (NT - 1);
        float dt = 1.0f;
        if (t > 0) dt = ts[i] - ts[i - 1];
        g_dtT[t * NB + b] = fmaxf(dt, 1e-6f);
    }
    if (i < NG * NH * GB) { g_h0x[i] = 0.f; g_h1x[i] = 0.f; }   // h(-1) = 0
    if (blockIdx.x < 64) {
        const int kq = blockIdx.x, o = tid;
        const int k0 = kq * 4;
        const int rank = o >> 5, ol = o & 31;
        const int idx = (rank * 64 + kq) * 32 + ol;
        { const float* p = gh_w0 + o * NH + k0;
          g_WA0[idx] = make_float4(p[0], p[1], p[2], p[3]); }
        { const float* p = bb_w0 + o * (NS + NH) + NS + k0;
          g_WA1[idx] = make_float4(p[0], p[1], p[2], p[3]); }
        { const float* p = gh_w1 + o * NH + k0;
          g_WH0[idx] = make_float4(p[0], p[1], p[2], p[3]); }
        { const float* p = bb_w1 + o * (2 * NH) + NH + k0;
          g_WH1[idx] = make_float4(p[0], p[1], p[2], p[3]); }
        { const float* p = gx_w1 + o * NH + k0;
          g_WX1g[idx] = make_float4(p[0], p[1], p[2], p[3]); }
        { const float* p = bb_w1 + o * (2 * NH) + k0;
          g_WX1b[idx] = make_float4(p[0], p[1], p[2], p[3]); }
        if (kq < 8)
            g_wx0[(rank * 8 + kq) * 32 + ol] =
                make_float2(gx_w0[o * NS + kq], bb_w0[o * (NS + NH) + kq]);
        if (kq == 0) {
            g_bias[0 * NH + o] = gx_b0[o] + gb0[o];
            g_bias[1 * NH + o] = bb_b0[o];
            g_bias[2 * NH + o] = log1pf(expf(lt0[o]));
            g_bias[3 * NH + o] = gx_b1[o] + gb1[o];
            g_bias[4 * NH + o] = bb_b1[o];
            g_bias[5 * NH + o] = log1pf(expf(lt1[o]));
        }
    }
    if (blockIdx.x == 64 && tid < NG) g_bar[tid] = 0u;
}

// ---------------------------------------------------------------------------
__device__ __forceinline__ void ffma2(ull& acc, ull a, ull b) {
    asm("fma.rn.f32x2 %0, %1, %2, %0;" : "+l"(acc) : "l"(a), "l"(b));
}
__device__ __forceinline__ void add2(ull& a, ull b) {
    asm("add.rn.f32x2 %0, %0, %1;" : "+l"(a) : "l"(b));
}
__device__ __forceinline__ ull splat2(float v) {
    ull r; asm("mov.b64 %0, {%1,%1};" : "=l"(r) : "f"(v)); return r;
}
__device__ __forceinline__ void unpack2(ull v, float& lo, float& hi) {
    asm("mov.b64 {%0,%1}, %2;" : "=f"(lo), "=f"(hi) : "l"(v));
}
__device__ __forceinline__ float fast_tanh(float x) {
    float y; asm("tanh.approx.f32 %0, %1;" : "=f"(y) : "f"(x)); return y;
}
__device__ __forceinline__ float cfc_one(float ag, float af, float sp, float dt, float hold) {
    const float g = __fdividef(1.f, 1.f + __expf(-ag));
    const float f = fast_tanh(af);
    const float d = __expf(-dt * (sp + fabsf(g)));
    return d * hold + (1.f - d) * f;
}
__device__ __forceinline__ unsigned ld_acq(const unsigned* p) {
    unsigned v;
    asm volatile("ld.acquire.gpu.global.u32 %0, [%1];" : "=r"(v) : "l"(p) : "memory");
    return v;
}
__device__ __forceinline__ void red_release(unsigned* p) {
    asm volatile("red.add.release.gpu.global.u32 [%0], %1;" :: "l"(p), "r"(1u) : "memory");
}

// one k-column MAC: splat weights, 8 batch-pair FFMA2 per stream
#define ACCK(WGC, WBC, HBASE, KIDX) do {                                      \
    const ull sg_ = splat2(WGC);                                              \
    const ull sb_ = splat2(WBC);                                              \
    const ulonglong2* hr_ = (const ulonglong2*)((HBASE) + (KIDX) * GB);       \
    const ulonglong2 p0_ = hr_[0], p1_ = hr_[1], p2_ = hr_[2], p3_ = hr_[3];  \
    ffma2(ag[0], sg_, p0_.x); ffma2(af[0], sb_, p0_.x);                       \
    ffma2(ag[1], sg_, p0_.y); ffma2(af[1], sb_, p0_.y);                       \
    ffma2(ag[2], sg_, p1_.x); ffma2(af[2], sb_, p1_.x);                       \
    ffma2(ag[3], sg_, p1_.y); ffma2(af[3], sb_, p1_.y);                       \
    ffma2(ag[4], sg_, p2_.x); ffma2(af[4], sb_, p2_.x);                       \
    ffma2(ag[5], sg_, p2_.y); ffma2(af[5], sb_, p2_.y);                       \
    ffma2(ag[6], sg_, p3_.x); ffma2(af[6], sb_, p3_.x);                       \
    ffma2(ag[7], sg_, p3_.y); ffma2(af[7], sb_, p3_.y);                       \
} while (0)

// SMEM byte offsets
#define OFF_WA0 0
#define OFF_WA1 32768
#define OFF_WH0 65536
#define OFF_WH1 98304
#define OFF_H0  131072        // [2][256][16] f32 = 32768 (double-buffered)
#define OFF_H1  163840        // [256][16] f32 = 16384
#define OFF_RED 180224        // [8][8][32] ulonglong2 = 32768
#define OFF_XN  212992        // [2][8][16] f32 = 1024 (double-buffered)
#define OFF_DT  214016        // [2][16] f32 = 128
#define OFF_LAT 214144        // 256
#define OFF_LN  214400        // 64
#define SMEM_BYTES 214464

__global__ void __launch_bounds__(NTHR, 1)
liquid_main_kernel(
    const float* __restrict__ xs,
    const float* __restrict__ ln_g, const float* __restrict__ ln_b,
    const float* __restrict__ lp_w, const float* __restrict__ lp_b,
    const float* __restrict__ r1_w, const float* __restrict__ r1_b,
    const float* __restrict__ r2_w, const float* __restrict__ r2_b,
    float* __restrict__ out)
{
    extern __shared__ char smem[];
    const float4* WA0 = (const float4*)(smem + OFF_WA0);
    const float4* WA1 = (const float4*)(smem + OFF_WA1);
    const float4* WH0 = (const float4*)(smem + OFF_WH0);
    const float4* WH1 = (const float4*)(smem + OFF_WH1);
    float* h0s  = (float*)(smem + OFF_H0);        // [buf][k][b]
    float* h1s  = (float*)(smem + OFF_H1);        // [k][b]
    ulonglong2* red = (ulonglong2*)(smem + OFF_RED);   // [bp][ws][ol] (ag, af)
    float* xn_s = (float*)(smem + OFF_XN);        // [buf][k][b]
    float* dt_s = (float*)(smem + OFF_DT);        // [buf][b]
    float* lat_s = (float*)(smem + OFF_LAT);
    float* ln_s = (float*)(smem + OFF_LN);        // [0..7]=gamma, [8..15]=beta

    const int tid  = threadIdx.x;
    const int ol   = tid & 31;     // compute: owned output lane / epi: output
    const int ws   = tid >> 5;     // compute: k-segment / epi: batch-pair
    const int rank = blockIdx.x & 7;
    const int grp  = blockIdx.x >> 3;
    const int og   = rank * 32 + ol;
    const int batch0 = grp * GB;

    // ---- load resident weight slices into SMEM (coalesced) ----
    {
        const float4* s0 = g_WA0 + rank * 2048;  float4* d0 = (float4*)(smem + OFF_WA0);
        const float4* s1 = g_WA1 + rank * 2048;  float4* d1 = (float4*)(smem + OFF_WA1);
        const float4* s2 = g_WH0 + rank * 2048;  float4* d2 = (float4*)(smem + OFF_WH0);
        const float4* s3 = g_WH1 + rank * 2048;  float4* d3 = (float4*)(smem + OFF_WH1);
        for (int i = tid; i < 2048; i += NTHR) {
            d0[i] = s0[i]; d1[i] = s1[i]; d2[i] = s2[i]; d3[i] = s3[i];
        }
    }
    // zero h buffers (h(-1) = 0) + LN params to SMEM
    {
        float4* z0 = (float4*)h0s; float4* z1 = (float4*)h1s;
        const float4 zz = make_float4(0.f, 0.f, 0.f, 0.f);
        for (int i = tid; i < 2048; i += NTHR) z0[i] = zz;     // both h0 bufs
        for (int i = tid; i < 1024; i += NTHR) z1[i] = zz;
        if (tid < NS) { ln_s[tid] = ln_g[tid]; ln_s[8 + tid] = ln_b[tid]; }
    }

    // persistent register weights: cell1 x-part (this thread's 8 kq)
    float4 wx1g_q[8], wx1b_q[8];
    #pragma unroll
    for (int j = 0; j < 8; j++) {
        wx1g_q[j] = g_WX1g[(rank * 64 + ws * 8 + j) * 32 + ol];
        wx1b_q[j] = g_WX1b[(rank * 64 + ws * 8 + j) * 32 + ol];
    }
    // cell0 x-part (k = ws only), pre-splatted
    ull wx0g2, wx0b2;
    {
        const float2 w = g_wx0[(rank * 8 + ws) * 32 + ol];
        wx0g2 = splat2(w.x); wx0b2 = splat2(w.y);
    }
    // biases for epilogue role
    const float bg0 = g_bias[0 * NH + og];
    const float bf0 = g_bias[1 * NH + og];
    const float sp0 = g_bias[2 * NH + og];
    const float bg1 = g_bias[3 * NH + og];
    const float bf1 = g_bias[4 * NH + og];
    const float sp1 = g_bias[5 * NH + og];

    // ---- initial xn(0)/dt(0) into buf 0, prefetch x(1)/dt(1) ----
    float4 px0, px1; float pdt = 1.f;
    if (tid < GB) {
        const float4* xp = (const float4*)(xs + (size_t)(batch0 + tid) * NT * NS);
        float4 a = xp[0], c = xp[1];
        float x[NS] = {a.x, a.y, a.z, a.w, c.x, c.y, c.z, c.w};
        float mu = 0.f;
        #pragma unroll
        for (int k = 0; k < NS; k++) mu += x[k];
        mu *= 0.125f;
        float var = 0.f;
        #pragma unroll
        for (int k = 0; k < NS; k++) { float d = x[k] - mu; var += d * d; }
        var *= 0.125f;
        const float inv = rsqrtf(var + 1e-5f);
        #pragma unroll
        for (int k = 0; k < NS; k++)
            xn_s[k * GB + tid] = (x[k] - mu) * inv * ln_g[k] + ln_b[k];
        dt_s[tid] = g_dtT[0 * NB + batch0 + tid];
        px0 = xp[2]; px1 = xp[3];          // x(1)
        pdt = g_dtT[1 * NB + batch0 + tid];
    }
    __syncthreads();

    const int lane = tid & 31;

    for (int t = 0; t < NT; t++) {
        const int bA = t & 1;
        float* h0old = h0s + bA * 4096;
        float* h0new = h0s + (bA ^ 1) * 4096;
        const float* xnc = xn_s + bA * 128;
        const float* dtc = dt_s + bA * GB;

        // ---- LN for step t+1 into buf bA^1 (no sync; consumed after 2 block syncs)
        if (tid < GB) {
            float x[NS] = {px0.x, px0.y, px0.z, px0.w, px1.x, px1.y, px1.z, px1.w};
            float mu = 0.f;
            #pragma unroll
            for (int k = 0; k < NS; k++) mu += x[k];
            mu *= 0.125f;
            float var = 0.f;
            #pragma unroll
            for (int k = 0; k < NS; k++) { float d = x[k] - mu; var += d * d; }
            var *= 0.125f;
            const float inv = rsqrtf(var + 1e-5f);
            float* xnn = xn_s + (bA ^ 1) * 128;
            #pragma unroll
            for (int k = 0; k < NS; k++)
                xnn[k * GB + tid] = (x[k] - mu) * inv * ln_s[k] + ln_s[8 + k];
            dt_s[(bA ^ 1) * GB + tid] = pdt;
            // prefetch x(t+2)/dt(t+2)
            const int tt = (t + 2 < NT) ? t + 2 : NT - 1;
            const float4* xp = (const float4*)(xs + ((size_t)(batch0 + tid) * NT + tt) * NS);
            px0 = xp[0]; px1 = xp[1];
            pdt = g_dtT[tt * NB + batch0 + tid];
        }

        // =================== stage A: CfC cell 0 (h0 = h0(t-1), buf bA) ============
        ull ag[8], af[8];
        #pragma unroll
        for (int bp = 0; bp < 8; bp++) { ag[bp] = 0ull; af[bp] = 0ull; }
        {   // x-part: warp ws handles sensor k = ws (xn buf bA, written step t-1)
            const ulonglong2* xr = (const ulonglong2*)(xnc + ws * GB);
            const ulonglong2 q0 = xr[0], q1 = xr[1], q2 = xr[2], q3 = xr[3];
            ffma2(ag[0], wx0g2, q0.x); ffma2(af[0], wx0b2, q0.x);
            ffma2(ag[1], wx0g2, q0.y); ffma2(af[1], wx0b2, q0.y);
            ffma2(ag[2], wx0g2, q1.x); ffma2(af[2], wx0b2, q1.x);
            ffma2(ag[3], wx0g2, q1.y); ffma2(af[3], wx0b2, q1.y);
            ffma2(ag[4], wx0g2, q2.x); ffma2(af[4], wx0b2, q2.x);
            ffma2(ag[5], wx0g2, q2.y); ffma2(af[5], wx0b2, q2.y);
            ffma2(ag[6], wx0g2, q3.x); ffma2(af[6], wx0b2, q3.x);
            ffma2(ag[7], wx0g2, q3.y); ffma2(af[7], wx0b2, q3.y);
        }
        #pragma unroll 4
        for (int kq = 0; kq < 8; kq++) {
            const int kqg = ws * 8 + kq;
            const float4 wg4 = WA0[kqg * 32 + ol];
            const float4 wb4 = WA1[kqg * 32 + ol];
            const int k0 = kqg * 4;
            ACCK(wg4.x, wb4.x, h0old, k0 + 0);
            ACCK(wg4.y, wb4.y, h0old, k0 + 1);
            ACCK(wg4.z, wb4.z, h0old, k0 + 2);
            ACCK(wg4.w, wb4.w, h0old, k0 + 3);
        }
        #pragma unroll
        for (int bp = 0; bp < 8; bp++)
            red[(bp * 8 + ws) * 32 + ol] = make_ulonglong2(ag[bp], af[bp]);
        __syncthreads();   // S2a
        {   // epilogue A: (output og, batch-pair bp = ws); hold from h0old
            const int bp = ws;
            ull g2 = 0ull, f2 = 0ull;
            #pragma unroll
            for (int w2 = 0; w2 < 8; w2++) {
                const ulonglong2 v = red[(bp * 8 + w2) * 32 + ol];
                add2(g2, v.x); add2(f2, v.y);
            }
            float gA, gB, fA, fB, hA, hB;
            unpack2(g2, gA, gB); unpack2(f2, fA, fB);
            const ull holdp = *(const ull*)(h0old + og * GB + 2 * bp);
            unpack2(holdp, hA, hB);
            const float hnA = cfc_one(gA + bg0, fA + bf0, sp0, dtc[2 * bp + 0], hA);
            const float hnB = cfc_one(gB + bg0, fB + bf0, sp0, dtc[2 * bp + 1], hB);
            *(float2*)(g_h0x + ((size_t)grp * NH + og) * GB + 2 * bp) = make_float2(hnA, hnB);
        }
        __syncwarp();
        if (lane == 0) red_release(&g_bar[grp]);     // arrive bar0(t): +8/CTA
        // ---- per-warp: wait bar1(t-1) (armed last step, fast) + reload h1 seg ----
        if (lane == 0) {
            const unsigned tgt = 64u * (unsigned)(2 * t);
            while (ld_acq(&g_bar[grp]) < tgt) {}
        }
        __syncwarp();
        {
            const float4* src = (const float4*)(g_h1x + (size_t)grp * NH * GB) + ws * 128;
            float4* dst = (float4*)(h1s) + ws * 128;
            #pragma unroll
            for (int j = 0; j < 4; j++) dst[lane + 32 * j] = __ldcg(src + lane + 32 * j);
        }
        __syncwarp();

        // ============ stage B part 1: h-contribution (old h1, own seg) =============
        #pragma unroll
        for (int bp = 0; bp < 8; bp++) { ag[bp] = 0ull; af[bp] = 0ull; }
        #pragma unroll 4
        for (int kq = 0; kq < 8; kq++) {
            const int kqg = ws * 8 + kq;
            const float4 wg4 = WH0[kqg * 32 + ol];
            const float4 wb4 = WH1[kqg * 32 + ol];
            const int k0 = kqg * 4;
            ACCK(wg4.x, wb4.x, h1s, k0 + 0);
            ACCK(wg4.y, wb4.y, h1s, k0 + 1);
            ACCK(wg4.z, wb4.z, h1s, k0 + 2);
            ACCK(wg4.w, wb4.w, h1s, k0 + 3);
        }
        // ---- per-warp: wait bar0(t) + reload h0 seg into buf bA^1 ----
        if (lane == 0) {
            const unsigned tgt = 64u * (unsigned)(2 * t + 1);
            while (ld_acq(&g_bar[grp]) < tgt) {}
        }
        __syncwarp();
        {
            const float4* src = (const float4*)(g_h0x + (size_t)grp * NH * GB) + ws * 128;
            float4* dst = (float4*)(h0new) + ws * 128;
            #pragma unroll
            for (int j = 0; j < 4; j++) dst[lane + 32 * j] = __ldcg(src + lane + 32 * j);
        }
        __syncwarp();

        // ============ stage B part 2: x-contribution (new h0, register weights) ====
        #pragma unroll
        for (int j = 0; j < 8; j++) {
            const float4 wg4 = wx1g_q[j];
            const float4 wb4 = wx1b_q[j];
            const int k0 = (ws * 8 + j) * 4;
            ACCK(wg4.x, wb4.x, h0new, k0 + 0);
            ACCK(wg4.y, wb4.y, h0new, k0 + 1);
            ACCK(wg4.z, wb4.z, h0new, k0 + 2);
            ACCK(wg4.w, wb4.w, h0new, k0 + 3);
        }
        #pragma unroll
        for (int bp = 0; bp < 8; bp++)
            red[(bp * 8 + ws) * 32 + ol] = make_ulonglong2(ag[bp], af[bp]);
        __syncthreads();   // S2b
        {   // epilogue B: hold from h1s (= h1(t-1))
            const int bp = ws;
            ull g2 = 0ull, f2 = 0ull;
            #pragma unroll
            for (int w2 = 0; w2 < 8; w2++) {
                const ulonglong2 v = red[(bp * 8 + w2) * 32 + ol];
                add2(g2, v.x); add2(f2, v.y);
            }
            float gA, gB, fA, fB, hA, hB;
            unpack2(g2, gA, gB); unpack2(f2, fA, fB);
            const ull holdp = *(const ull*)(h1s + og * GB + 2 * bp);
            unpack2(holdp, hA, hB);
            const float hnA = cfc_one(gA + bg1, fA + bf1, sp1, dtc[2 * bp + 0], hA);
            const float hnB = cfc_one(gB + bg1, fB + bf1, sp1, dtc[2 * bp + 1], hB);
            *(float2*)(g_h1x + ((size_t)grp * NH + og) * GB + 2 * bp) = make_float2(hnA, hnB);
        }
        __syncwarp();
        if (lane == 0) red_release(&g_bar[grp]);     // arrive bar1(t); wait deferred
    }

    // ---- final: per-warp wait last bar1, reload own h1 seg, join, head ----
    if (lane == 0) {
        const unsigned tgt = 64u * (unsigned)(2 * NT);
        while (ld_acq(&g_bar[grp]) < tgt) {}
    }
    __syncwarp();
    {
        const float4* src = (const float4*)(g_h1x + (size_t)grp * NH * GB) + ws * 128;
        float4* dst = (float4*)(h1s) + ws * 128;
        #pragma unroll
        for (int j = 0; j < 4; j++) dst[lane + 32 * j] = __ldcg(src + lane + 32 * j);
    }
    __syncthreads();

    // =================== head: latent + risk (2 batches per CTA) ===================
    if (tid < 64) {
        const int i = tid >> 5, l = tid & 31;
        const int lb = rank * 2 + i;
        const int gb = batch0 + lb;
        const float* wrow = lp_w + l * NH;
        float acc = lp_b[l];
        for (int k = 0; k < NH; k++) acc = fmaf(h1s[k * GB + lb], __ldg(wrow + k), acc);
        const float latv = tanhf(acc);
        lat_s[i * 32 + l] = latv;
        out[(size_t)gb * 32 + l] = latv;
    }
    __syncthreads();
    if (tid < 64) {
        const int i = tid >> 5, j = tid & 31;
        const int gb = batch0 + rank * 2 + i;
        const float* wrow = r1_w + j * 32;
        float acc = r1_b[j];
        #pragma unroll
        for (int k = 0; k < 32; k++) acc = fmaf(lat_s[i * 32 + k], __ldg(wrow + k), acc);
        const float hid = 0.5f * acc * (1.f + erff(acc * 0.70710678118654752f));
        float v = hid * __ldg(r2_w + j);
        #pragma unroll
        for (int off = 16; off; off >>= 1) v += __shfl_xor_sync(0xffffffffu, v, off);
        if (j == 0) {
            const float risk = 1.f / (1.f + __expf(-(v + r2_b[0])));
            out[NB * 32 + gb] = risk;
        }
    }
}

// ---------------------------------------------------------------------------
extern "C" void kernel_launch(void* const* d_in, const int* in_sizes, int n_in,
                              void* d_out, int out_size) {
    const float* xs    = (const float*)d_in[0];
    const float* ts    = (const float*)d_in[1];
    const float* ln_g  = (const float*)d_in[2];
    const float* ln_b  = (const float*)d_in[3];
    const float* bb_w0 = (const float*)d_in[4];
    const float* bb_b0 = (const float*)d_in[5];
    const float* gx_w0 = (const float*)d_in[6];
    const float* gx_b0 = (const float*)d_in[7];
    const float* gh_w0 = (const float*)d_in[8];
    const float* gb0   = (const float*)d_in[9];
    const float* lt0   = (const float*)d_in[10];
    const float* bb_w1 = (const float*)d_in[11];
    const float* bb_b1 = (const float*)d_in[12];
    const float* gx_w1 = (const float*)d_in[13];
    const float* gx_b1 = (const float*)d_in[14];
    const float* gh_w1 = (const float*)d_in[15];
    const float* gb1   = (const float*)d_in[16];
    const float* lt1   = (const float*)d_in[17];
    const float* lp_w  = (const float*)d_in[18];
    const float* lp_b  = (const float*)d_in[19];
    const float* r1_w  = (const float*)d_in[20];
    const float* r1_b  = (const float*)d_in[21];
    const float* r2_w  = (const float*)d_in[22];
    const float* r2_b  = (const float*)d_in[23];
    float* out = (float*)d_out;

    cudaFuncSetAttribute(liquid_main_kernel,
                         cudaFuncAttributeMaxDynamicSharedMemorySize, SMEM_BYTES);

    prep_kernel<<<1024, 256>>>(ts, bb_w0, gx_w0, gx_b0, gh_w0, gb0, lt0,
                               bb_w1, gx_w1, gx_b1, gh_w1, gb1, lt1,
                               bb_b0, bb_b1);
    liquid_main_kernel<<<NCTA, NTHR, SMEM_BYTES>>>(
        xs, ln_g, ln_b, lp_w, lp_b, r1_w, r1_b, r2_w, r2_b, out);
}

// round 13
// speedup vs baseline: 1.2706x; 1.2706x over previous
#include <cuda_runtime.h>
#include <math.h>
#include <stdint.h>

// LiquidNNSensorModel: 2-layer CfC RNN, B=256, T=1024, S=8, H=256.
// R13: R11 base (SMEM weights, 16 groups x 8 ranks, L2 exchange, 1 release-red
// arrival per CTA per phase) + per-warp acquire-waits and warp-local segment
// reloads hidden in compute shadows. 4 block syncs/step. xn double-buffered,
// h0s SMEM double-buffered. h0 reload via registers across B1b.

#define NB 256
#define NT 1024
#define NS 8
#define NH 256
#define NG 16        // groups
#define CSZ 8        // CTAs (ranks) per group
#define GB 16        // batches per group
#define NCTA 128
#define NTHR 256

typedef unsigned long long ull;

// ---- global scratch ----
__device__ float4 g_WA0[CSZ * 64 * 32];   // [rank][kq][ol] gh_w0 quads
__device__ float4 g_WA1[CSZ * 64 * 32];   // bb_w0 h-part
__device__ float4 g_WH0[CSZ * 64 * 32];   // gh_w1
__device__ float4 g_WH1[CSZ * 64 * 32];   // bb_w1 h-part
__device__ float4 g_WX1g[CSZ * 64 * 32];  // gx_w1
__device__ float4 g_WX1b[CSZ * 64 * 32];  // bb_w1 x-part
__device__ float2 g_wx0[CSZ * 8 * 32];    // [rank][k][ol] (gx_w0, bb_w0_x)
__device__ float  g_bias[6 * NH];
__device__ float  g_dtT[NT * NB];         // [t][b]
__device__ float  g_h0x[NG * NH * GB];    // exchange: [grp][k][b]
__device__ float  g_h1x[NG * NH * GB];
__device__ unsigned g_bar[NG];

// ---------------------------------------------------------------------------
__global__ void prep_kernel(
    const float* __restrict__ ts,
    const float* __restrict__ bb_w0, const float* __restrict__ gx_w0,
    const float* __restrict__ gx_b0, const float* __restrict__ gh_w0,
    const float* __restrict__ gb0,   const float* __restrict__ lt0,
    const float* __restrict__ bb_w1, const float* __restrict__ gx_w1,
    const float* __restrict__ gx_b1, const float* __restrict__ gh_w1,
    const float* __restrict__ gb1,   const float* __restrict__ lt1,
    const float* __restrict__ bb_b0, const float* __restrict__ bb_b1)
{
    const int tid = threadIdx.x;
    const int i = blockIdx.x * blockDim.x + tid;
    {   // dt transpose
        const int b = i >> 10, t = i & (NT - 1);
        float dt = 1.0f;
        if (t > 0) dt = ts[i] - ts[i - 1];
        g_dtT[t * NB + b] = fmaxf(dt, 1e-6f);
    }
    if (i < NG * NH * GB) { g_h0x[i] = 0.f; g_h1x[i] = 0.f; }   // h(-1) = 0
    if (blockIdx.x < 64) {
        const int kq = blockIdx.x, o = tid;
        const int k0 = kq * 4;
        const int rank = o >> 5, ol = o & 31;
        const int idx = (rank * 64 + kq) * 32 + ol;
        { const float* p = gh_w0 + o * NH + k0;
          g_WA0[idx] = make_float4(p[0], p[1], p[2], p[3]); }
        { const float* p = bb_w0 + o * (NS + NH) + NS + k0;
          g_WA1[idx] = make_float4(p[0], p[1], p[2], p[3]); }
        { const float* p = gh_w1 + o * NH + k0;
          g_WH0[idx] = make_float4(p[0], p[1], p[2], p[3]); }
        { const float* p = bb_w1 + o * (2 * NH) + NH + k0;
          g_WH1[idx] = make_float4(p[0], p[1], p[2], p[3]); }
        { const float* p = gx_w1 + o * NH + k0;
          g_WX1g[idx] = make_float4(p[0], p[1], p[2], p[3]); }
        { const float* p = bb_w1 + o * (2 * NH) + k0;
          g_WX1b[idx] = make_float4(p[0], p[1], p[2], p[3]); }
        if (kq < 8)
            g_wx0[(rank * 8 + kq) * 32 + ol] =
                make_float2(gx_w0[o * NS + kq], bb_w0[o * (NS + NH) + kq]);
        if (kq == 0) {
            g_bias[0 * NH + o] = gx_b0[o] + gb0[o];
            g_bias[1 * NH + o] = bb_b0[o];
            g_bias[2 * NH + o] = log1pf(expf(lt0[o]));
            g_bias[3 * NH + o] = gx_b1[o] + gb1[o];
            g_bias[4 * NH + o] = bb_b1[o];
            g_bias[5 * NH + o] = log1pf(expf(lt1[o]));
        }
    }
    if (blockIdx.x == 64 && tid < NG) g_bar[tid] = 0u;
}

// ---------------------------------------------------------------------------
__device__ __forceinline__ void ffma2(ull& acc, ull a, ull b) {
    asm("fma.rn.f32x2 %0, %1, %2, %0;" : "+l"(acc) : "l"(a), "l"(b));
}
__device__ __forceinline__ void add2(ull& a, ull b) {
    asm("add.rn.f32x2 %0, %0, %1;" : "+l"(a) : "l"(b));
}
__device__ __forceinline__ ull splat2(float v) {
    ull r; asm("mov.b64 %0, {%1,%1};" : "=l"(r) : "f"(v)); return r;
}
__device__ __forceinline__ void unpack2(ull v, float& lo, float& hi) {
    asm("mov.b64 {%0,%1}, %2;" : "=f"(lo), "=f"(hi) : "l"(v));
}
__device__ __forceinline__ float fast_tanh(float x) {
    float y; asm("tanh.approx.f32 %0, %1;" : "=f"(y) : "f"(x)); return y;
}
__device__ __forceinline__ float cfc_one(float ag, float af, float sp, float dt, float hold) {
    const float g = __fdividef(1.f, 1.f + __expf(-ag));
    const float f = fast_tanh(af);
    const float d = __expf(-dt * (sp + fabsf(g)));
    return d * hold + (1.f - d) * f;
}
__device__ __forceinline__ unsigned ld_acq(const unsigned* p) {
    unsigned v;
    asm volatile("ld.acquire.gpu.global.u32 %0, [%1];" : "=r"(v) : "l"(p) : "memory");
    return v;
}
__device__ __forceinline__ void red_release(unsigned* p) {
    asm volatile("red.add.release.gpu.global.u32 [%0], %1;" :: "l"(p), "r"(1u) : "memory");
}

// one k-column MAC: splat weights, 8 batch-pair FFMA2 per stream
#define ACCK(WGC, WBC, HBASE, KIDX) do {                                      \
    const ull sg_ = splat2(WGC);                                              \
    const ull sb_ = splat2(WBC);                                              \
    const ulonglong2* hr_ = (const ulonglong2*)((HBASE) + (KIDX) * GB);       \
    const ulonglong2 p0_ = hr_[0], p1_ = hr_[1], p2_ = hr_[2], p3_ = hr_[3];  \
    ffma2(ag[0], sg_, p0_.x); ffma2(af[0], sb_, p0_.x);                       \
    ffma2(ag[1], sg_, p0_.y); ffma2(af[1], sb_, p0_.y);                       \
    ffma2(ag[2], sg_, p1_.x); ffma2(af[2], sb_, p1_.x);                       \
    ffma2(ag[3], sg_, p1_.y); ffma2(af[3], sb_, p1_.y);                       \
    ffma2(ag[4], sg_, p2_.x); ffma2(af[4], sb_, p2_.x);                       \
    ffma2(ag[5], sg_, p2_.y); ffma2(af[5], sb_, p2_.y);                       \
    ffma2(ag[6], sg_, p3_.x); ffma2(af[6], sb_, p3_.x);                       \
    ffma2(ag[7], sg_, p3_.y); ffma2(af[7], sb_, p3_.y);                       \
} while (0)

// SMEM byte offsets
#define OFF_WA0 0
#define OFF_WA1 32768
#define OFF_WH0 65536
#define OFF_WH1 98304
#define OFF_H0  131072        // [2][256][16] f32 = 32768 (double-buffered)
#define OFF_H1  163840        // [256][16] f32 = 16384
#define OFF_RED 180224        // [8][8][32] ulonglong2 = 32768
#define OFF_XN  212992        // [2][8][16] f32 = 1024 (double-buffered)
#define OFF_DT  214016        // [2][16] f32 = 128
#define OFF_LAT 214144        // 256
#define OFF_LN  214400        // 64
#define SMEM_BYTES 214464

__global__ void __launch_bounds__(NTHR, 1)
liquid_main_kernel(
    const float* __restrict__ xs,
    const float* __restrict__ ln_g, const float* __restrict__ ln_b,
    const float* __restrict__ lp_w, const float* __restrict__ lp_b,
    const float* __restrict__ r1_w, const float* __restrict__ r1_b,
    const float* __restrict__ r2_w, const float* __restrict__ r2_b,
    float* __restrict__ out)
{
    extern __shared__ char smem[];
    const float4* WA0 = (const float4*)(smem + OFF_WA0);
    const float4* WA1 = (const float4*)(smem + OFF_WA1);
    const float4* WH0 = (const float4*)(smem + OFF_WH0);
    const float4* WH1 = (const float4*)(smem + OFF_WH1);
    float* h0s  = (float*)(smem + OFF_H0);        // [buf][k][b]
    float* h1s  = (float*)(smem + OFF_H1);        // [k][b]
    ulonglong2* red = (ulonglong2*)(smem + OFF_RED);   // [bp][ws][ol]
    float* xn_s = (float*)(smem + OFF_XN);        // [buf][k][b]
    float* dt_s = (float*)(smem + OFF_DT);        // [buf][b]
    float* lat_s = (float*)(smem + OFF_LAT);
    float* ln_s = (float*)(smem + OFF_LN);        // [0..7]=gamma, [8..15]=beta

    const int tid  = threadIdx.x;
    const int ol   = tid & 31;
    const int ws   = tid >> 5;          // k-segment / epi batch-pair
    const int lane = ol;
    const int rank = blockIdx.x & 7;
    const int grp  = blockIdx.x >> 3;
    const int og   = rank * 32 + ol;
    const int batch0 = grp * GB;

    // ---- load resident weight slices into SMEM (coalesced) ----
    {
        const float4* s0 = g_WA0 + rank * 2048;  float4* d0 = (float4*)(smem + OFF_WA0);
        const float4* s1 = g_WA1 + rank * 2048;  float4* d1 = (float4*)(smem + OFF_WA1);
        const float4* s2 = g_WH0 + rank * 2048;  float4* d2 = (float4*)(smem + OFF_WH0);
        const float4* s3 = g_WH1 + rank * 2048;  float4* d3 = (float4*)(smem + OFF_WH1);
        for (int i = tid; i < 2048; i += NTHR) {
            d0[i] = s0[i]; d1[i] = s1[i]; d2[i] = s2[i]; d3[i] = s3[i];
        }
    }
    // zero h buffers + LN params
    {
        float4* z0 = (float4*)h0s; float4* z1 = (float4*)h1s;
        const float4 zz = make_float4(0.f, 0.f, 0.f, 0.f);
        for (int i = tid; i < 2048; i += NTHR) z0[i] = zz;   // both h0 bufs
        for (int i = tid; i < 1024; i += NTHR) z1[i] = zz;
        if (tid < NS) { ln_s[tid] = ln_g[tid]; ln_s[8 + tid] = ln_b[tid]; }
    }

    // persistent register weights: cell1 x-part (this thread's 8 kq)
    float4 wx1g_q[8], wx1b_q[8];
    #pragma unroll
    for (int j = 0; j < 8; j++) {
        wx1g_q[j] = g_WX1g[(rank * 64 + ws * 8 + j) * 32 + ol];
        wx1b_q[j] = g_WX1b[(rank * 64 + ws * 8 + j) * 32 + ol];
    }
    // cell0 x-part (k = ws only), pre-splatted
    ull wx0g2, wx0b2;
    {
        const float2 w = g_wx0[(rank * 8 + ws) * 32 + ol];
        wx0g2 = splat2(w.x); wx0b2 = splat2(w.y);
    }
    // biases for epilogue role
    const float bg0 = g_bias[0 * NH + og];
    const float bf0 = g_bias[1 * NH + og];
    const float sp0 = g_bias[2 * NH + og];
    const float bg1 = g_bias[3 * NH + og];
    const float bf1 = g_bias[4 * NH + og];
    const float sp1 = g_bias[5 * NH + og];

    // ---- initial xn(0)/dt(0) into buf 0, prefetch x(1)/dt(1) ----
    float4 px0, px1; float pdt = 1.f;
    if (tid < GB) {
        const float4* xp = (const float4*)(xs + (size_t)(batch0 + tid) * NT * NS);
        float4 a = xp[0], c = xp[1];
        float x[NS] = {a.x, a.y, a.z, a.w, c.x, c.y, c.z, c.w};
        float mu = 0.f;
        #pragma unroll
        for (int k = 0; k < NS; k++) mu += x[k];
        mu *= 0.125f;
        float var = 0.f;
        #pragma unroll
        for (int k = 0; k < NS; k++) { float d = x[k] - mu; var += d * d; }
        var *= 0.125f;
        const float inv = rsqrtf(var + 1e-5f);
        #pragma unroll
        for (int k = 0; k < NS; k++)
            xn_s[k * GB + tid] = (x[k] - mu) * inv * ln_g[k] + ln_b[k];
        dt_s[tid] = g_dtT[0 * NB + batch0 + tid];
        px0 = xp[2]; px1 = xp[3];          // x(1)
        pdt = g_dtT[1 * NB + batch0 + tid];
    }
    __syncthreads();

    const float4* h1src = (const float4*)(g_h1x + (size_t)grp * NH * GB) + ws * 128;
    const float4* h0src = (const float4*)(g_h0x + (size_t)grp * NH * GB) + ws * 128;
    float4* h1dst = (float4*)h1s + ws * 128;

    for (int t = 0; t < NT; t++) {
        const int bA = t & 1;
        float* h0old = h0s + bA * 4096;
        float* h0new = h0s + (bA ^ 1) * 4096;
        const float* xnc = xn_s + bA * 128;
        const float* dtc = dt_s + bA * GB;

        // ---- LN(t+1) into buf bA^1 (no sync; consumed next step after S2..S9) ----
        if (tid < GB) {
            float x[NS] = {px0.x, px0.y, px0.z, px0.w, px1.x, px1.y, px1.z, px1.w};
            float mu = 0.f;
            #pragma unroll
            for (int k = 0; k < NS; k++) mu += x[k];
            mu *= 0.125f;
            float var = 0.f;
            #pragma unroll
            for (int k = 0; k < NS; k++) { float d = x[k] - mu; var += d * d; }
            var *= 0.125f;
            const float inv = rsqrtf(var + 1e-5f);
            float* xnn = xn_s + (bA ^ 1) * 128;
            #pragma unroll
            for (int k = 0; k < NS; k++)
                xnn[k * GB + tid] = (x[k] - mu) * inv * ln_s[k] + ln_s[8 + k];
            dt_s[(bA ^ 1) * GB + tid] = pdt;
            const int tt = (t + 2 < NT) ? t + 2 : NT - 1;
            const float4* xp = (const float4*)(xs + ((size_t)(batch0 + tid) * NT + tt) * NS);
            px0 = xp[0]; px1 = xp[1];
            pdt = g_dtT[tt * NB + batch0 + tid];
        }

        // =================== stage A: CfC cell 0 (h0old = h0(t-1)) =================
        ull ag[8], af[8];
        #pragma unroll
        for (int bp = 0; bp < 8; bp++) { ag[bp] = 0ull; af[bp] = 0ull; }
        {   // x-part: warp ws handles sensor k = ws (xn buf bA, written step t-1)
            const ulonglong2* xr = (const ulonglong2*)(xnc + ws * GB);
            const ulonglong2 q0 = xr[0], q1 = xr[1], q2 = xr[2], q3 = xr[3];
            ffma2(ag[0], wx0g2, q0.x); ffma2(af[0], wx0b2, q0.x);
            ffma2(ag[1], wx0g2, q0.y); ffma2(af[1], wx0b2, q0.y);
            ffma2(ag[2], wx0g2, q1.x); ffma2(af[2], wx0b2, q1.x);
            ffma2(ag[3], wx0g2, q1.y); ffma2(af[3], wx0b2, q1.y);
            ffma2(ag[4], wx0g2, q2.x); ffma2(af[4], wx0b2, q2.x);
            ffma2(ag[5], wx0g2, q2.y); ffma2(af[5], wx0b2, q2.y);
            ffma2(ag[6], wx0g2, q3.x); ffma2(af[6], wx0b2, q3.x);
            ffma2(ag[7], wx0g2, q3.y); ffma2(af[7], wx0b2, q3.y);
        }
        #pragma unroll 4
        for (int kq = 0; kq < 8; kq++) {
            const int kqg = ws * 8 + kq;
            const float4 wg4 = WA0[kqg * 32 + ol];
            const float4 wb4 = WA1[kqg * 32 + ol];
            const int k0 = kqg * 4;
            ACCK(wg4.x, wb4.x, h0old, k0 + 0);
            ACCK(wg4.y, wb4.y, h0old, k0 + 1);
            ACCK(wg4.z, wb4.z, h0old, k0 + 2);
            ACCK(wg4.w, wb4.w, h0old, k0 + 3);
        }

        // ---- per-warp: wait bar1(t-1) (stage A gave slack) + reload own h1 seg ----
        if (lane == 0) {
            const unsigned tgt = 16u * (unsigned)t;
            while (ld_acq(&g_bar[grp]) < tgt) {}
        }
        __syncwarp();
        {
            h1dst[lane]       = __ldcg(h1src + lane);
            h1dst[lane + 32]  = __ldcg(h1src + lane + 32);
            h1dst[lane + 64]  = __ldcg(h1src + lane + 64);
            h1dst[lane + 96]  = __ldcg(h1src + lane + 96);
        }
        __syncwarp();

        #pragma unroll
        for (int bp = 0; bp < 8; bp++)
            red[(bp * 8 + ws) * 32 + ol] = make_ulonglong2(ag[bp], af[bp]);
        __syncthreads();   // S2
        {   // epilogue A: (output og, batch-pair bp = ws); hold from h0old (buf bA)
            const int bp = ws;
            ull g2 = 0ull, f2 = 0ull;
            #pragma unroll
            for (int w2 = 0; w2 < 8; w2++) {
                const ulonglong2 v = red[(bp * 8 + w2) * 32 + ol];
                add2(g2, v.x); add2(f2, v.y);
            }
            float gA, gB, fA, fB, hA, hB;
            unpack2(g2, gA, gB); unpack2(f2, fA, fB);
            const ull holdp = *(const ull*)(h0old + og * GB + 2 * bp);
            unpack2(holdp, hA, hB);
            const float hnA = cfc_one(gA + bg0, fA + bf0, sp0, dtc[2 * bp + 0], hA);
            const float hnB = cfc_one(gB + bg0, fB + bf0, sp0, dtc[2 * bp + 1], hB);
            *(float2*)(g_h0x + ((size_t)grp * NH + og) * GB + 2 * bp) = make_float2(hnA, hnB);
        }
        __syncthreads();   // S3 — all h0 STGs issued
        if (tid == 0) red_release(&g_bar[grp]);   // arrive bar0(t)

        // ============ stage B part 1a: h-contribution (h1s = h1(t-1)), kq 0..5 =====
        #pragma unroll
        for (int bp = 0; bp < 8; bp++) { ag[bp] = 0ull; af[bp] = 0ull; }
        #pragma unroll
        for (int kq = 0; kq < 6; kq++) {
            const int kqg = ws * 8 + kq;
            const float4 wg4 = WH0[kqg * 32 + ol];
            const float4 wb4 = WH1[kqg * 32 + ol];
            const int k0 = kqg * 4;
            ACCK(wg4.x, wb4.x, h1s, k0 + 0);
            ACCK(wg4.y, wb4.y, h1s, k0 + 1);
            ACCK(wg4.z, wb4.z, h1s, k0 + 2);
            ACCK(wg4.w, wb4.w, h1s, k0 + 3);
        }
        // ---- per-warp: wait bar0(t), LDG own h0 seg to regs (hidden by B1b) ----
        if (lane == 0) {
            const unsigned tgt = 16u * (unsigned)t + 8u;
            while (ld_acq(&g_bar[grp]) < tgt) {}
        }
        __syncwarp();
        float4 r0 = __ldcg(h0src + lane);
        float4 r1 = __ldcg(h0src + lane + 32);
        float4 r2 = __ldcg(h0src + lane + 64);
        float4 r3 = __ldcg(h0src + lane + 96);
        // ============ stage B part 1b: kq 6..7 (covers the LDG latency) ============
        #pragma unroll
        for (int kq = 6; kq < 8; kq++) {
            const int kqg = ws * 8 + kq;
            const float4 wg4 = WH0[kqg * 32 + ol];
            const float4 wb4 = WH1[kqg * 32 + ol];
            const int k0 = kqg * 4;
            ACCK(wg4.x, wb4.x, h1s, k0 + 0);
            ACCK(wg4.y, wb4.y, h1s, k0 + 1);
            ACCK(wg4.z, wb4.z, h1s, k0 + 2);
            ACCK(wg4.w, wb4.w, h1s, k0 + 3);
        }
        {   // store reloaded h0(t) into buf bA^1 (own segment)
            float4* d = (float4*)h0new + ws * 128;
            d[lane] = r0; d[lane + 32] = r1; d[lane + 64] = r2; d[lane + 96] = r3;
        }
        __syncwarp();

        // ============ stage B part 2: x-contribution (h0new, register weights) =====
        #pragma unroll
        for (int j = 0; j < 8; j++) {
            const float4 wg4 = wx1g_q[j];
            const float4 wb4 = wx1b_q[j];
            const int k0 = (ws * 8 + j) * 4;
            ACCK(wg4.x, wb4.x, h0new, k0 + 0);
            ACCK(wg4.y, wb4.y, h0new, k0 + 1);
            ACCK(wg4.z, wb4.z, h0new, k0 + 2);
            ACCK(wg4.w, wb4.w, h0new, k0 + 3);
        }
        #pragma unroll
        for (int bp = 0; bp < 8; bp++)
            red[(bp * 8 + ws) * 32 + ol] = make_ulonglong2(ag[bp], af[bp]);
        __syncthreads();   // S8
        {   // epilogue B: hold from h1s (= h1(t-1))
            const int bp = ws;
            ull g2 = 0ull, f2 = 0ull;
            #pragma unroll
            for (int w2 = 0; w2 < 8; w2++) {
                const ulonglong2 v = red[(bp * 8 + w2) * 32 + ol];
                add2(g2, v.x); add2(f2, v.y);
            }
            float gA, gB, fA, fB, hA, hB;
            unpack2(g2, gA, gB); unpack2(f2, fA, fB);
            const ull holdp = *(const ull*)(h1s + og * GB + 2 * bp);
            unpack2(holdp, hA, hB);
            const float hnA = cfc_one(gA + bg1, fA + bf1, sp1, dtc[2 * bp + 0], hA);
            const float hnB = cfc_one(gB + bg1, fB + bf1, sp1, dtc[2 * bp + 1], hB);
            *(float2*)(g_h1x + ((size_t)grp * NH + og) * GB + 2 * bp) = make_float2(hnA, hnB);
        }
        __syncthreads();   // S9 — h1 STGs issued; also fences h1s WAR for next reload
        if (tid == 0) red_release(&g_bar[grp]);   // arrive bar1(t); wait deferred
    }

    // ---- final: per-warp wait last bar1, reload own h1 seg, join, head ----
    if (lane == 0) {
        const unsigned tgt = 16u * (unsigned)NT;
        while (ld_acq(&g_bar[grp]) < tgt) {}
    }
    __syncwarp();
    {
        h1dst[lane]       = __ldcg(h1src + lane);
        h1dst[lane + 32]  = __ldcg(h1src + lane + 32);
        h1dst[lane + 64]  = __ldcg(h1src + lane + 64);
        h1dst[lane + 96]  = __ldcg(h1src + lane + 96);
    }
    __syncthreads();

    // =================== head: latent + risk (2 batches per CTA) ===================
    if (tid < 64) {
        const int i = tid >> 5, l = tid & 31;
        const int lb = rank * 2 + i;
        const int gb = batch0 + lb;
        const float* wrow = lp_w + l * NH;
        float acc = lp_b[l];
        for (int k = 0; k < NH; k++) acc = fmaf(h1s[k * GB + lb], __ldg(wrow + k), acc);
        const float latv = tanhf(acc);
        lat_s[i * 32 + l] = latv;
        out[(size_t)gb * 32 + l] = latv;
    }
    __syncthreads();
    if (tid < 64) {
        const int i = tid >> 5, j = tid & 31;
        const int gb = batch0 + rank * 2 + i;
        const float* wrow = r1_w + j * 32;
        float acc = r1_b[j];
        #pragma unroll
        for (int k = 0; k < 32; k++) acc = fmaf(lat_s[i * 32 + k], __ldg(wrow + k), acc);
        const float hid = 0.5f * acc * (1.f + erff(acc * 0.70710678118654752f));
        float v = hid * __ldg(r2_w + j);
        #pragma unroll
        for (int off = 16; off; off >>= 1) v += __shfl_xor_sync(0xffffffffu, v, off);
        if (j == 0) {
            const float risk = 1.f / (1.f + __expf(-(v + r2_b[0])));
            out[NB * 32 + gb] = risk;
        }
    }
}

// ---------------------------------------------------------------------------
extern "C" void kernel_launch(void* const* d_in, const int* in_sizes, int n_in,
                              void* d_out, int out_size) {
    const float* xs    = (const float*)d_in[0];
    const float* ts    = (const float*)d_in[1];
    const float* ln_g  = (const float*)d_in[2];
    const float* ln_b  = (const float*)d_in[3];
    const float* bb_w0 = (const float*)d_in[4];
    const float* bb_b0 = (const float*)d_in[5];
    const float* gx_w0 = (const float*)d_in[6];
    const float* gx_b0 = (const float*)d_in[7];
    const float* gh_w0 = (const float*)d_in[8];
    const float* gb0   = (const float*)d_in[9];
    const float* lt0   = (const float*)d_in[10];
    const float* bb_w1 = (const float*)d_in[11];
    const float* bb_b1 = (const float*)d_in[12];
    const float* gx_w1 = (const float*)d_in[13];
    const float* gx_b1 = (const float*)d_in[14];
    const float* gh_w1 = (const float*)d_in[15];
    const float* gb1   = (const float*)d_in[16];
    const float* lt1   = (const float*)d_in[17];
    const float* lp_w  = (const float*)d_in[18];
    const float* lp_b  = (const float*)d_in[19];
    const float* r1_w  = (const float*)d_in[20];
    const float* r1_b  = (const float*)d_in[21];
    const float* r2_w  = (const float*)d_in[22];
    const float* r2_b  = (const float*)d_in[23];
    float* out = (float*)d_out;

    cudaFuncSetAttribute(liquid_main_kernel,
                         cudaFuncAttributeMaxDynamicSharedMemorySize, SMEM_BYTES);

    prep_kernel<<<1024, 256>>>(ts, bb_w0, gx_w0, gx_b0, gh_w0, gb0, lt0,
                               bb_w1, gx_w1, gx_b1, gh_w1, gb1, lt1,
                               bb_b0, bb_b1);
    liquid_main_kernel<<<NCTA, NTHR, SMEM_BYTES>>>(
        xs, ln_g, ln_b, lp_w, lp_b, r1_w, r1_b, r2_w, r2_b, out);
}

// round 14
// speedup vs baseline: 1.2956x; 1.0196x over previous
#include <cuda_runtime.h>
#include <math.h>
#include <stdint.h>

// LiquidNNSensorModel: 2-layer CfC RNN, B=256, T=1024, S=8, H=256.
// R14: R13 + asymmetric post-epilogue barriers: warps arrive (non-blocking)
// and continue into compute; one designated warp syncs and issues the
// release-red arrival (warp 0 for bar0/S3, warp 7 for bar1/S9).

#define NB 256
#define NT 1024
#define NS 8
#define NH 256
#define NG 16        // groups
#define CSZ 8        // CTAs (ranks) per group
#define GB 16        // batches per group
#define NCTA 128
#define NTHR 256

typedef unsigned long long ull;

// ---- global scratch ----
__device__ float4 g_WA0[CSZ * 64 * 32];   // [rank][kq][ol] gh_w0 quads
__device__ float4 g_WA1[CSZ * 64 * 32];   // bb_w0 h-part
__device__ float4 g_WH0[CSZ * 64 * 32];   // gh_w1
__device__ float4 g_WH1[CSZ * 64 * 32];   // bb_w1 h-part
__device__ float4 g_WX1g[CSZ * 64 * 32];  // gx_w1
__device__ float4 g_WX1b[CSZ * 64 * 32];  // bb_w1 x-part
__device__ float2 g_wx0[CSZ * 8 * 32];    // [rank][k][ol] (gx_w0, bb_w0_x)
__device__ float  g_bias[6 * NH];
__device__ float  g_dtT[NT * NB];         // [t][b]
__device__ float  g_h0x[NG * NH * GB];    // exchange: [grp][k][b]
__device__ float  g_h1x[NG * NH * GB];
__device__ unsigned g_bar[NG];

// ---------------------------------------------------------------------------
__global__ void prep_kernel(
    const float* __restrict__ ts,
    const float* __restrict__ bb_w0, const float* __restrict__ gx_w0,
    const float* __restrict__ gx_b0, const float* __restrict__ gh_w0,
    const float* __restrict__ gb0,   const float* __restrict__ lt0,
    const float* __restrict__ bb_w1, const float* __restrict__ gx_w1,
    const float* __restrict__ gx_b1, const float* __restrict__ gh_w1,
    const float* __restrict__ gb1,   const float* __restrict__ lt1,
    const float* __restrict__ bb_b0, const float* __restrict__ bb_b1)
{
    const int tid = threadIdx.x;
    const int i = blockIdx.x * blockDim.x + tid;
    {   // dt transpose
        const int b = i >> 10, t = i & (NT - 1);
        float dt = 1.0f;
        if (t > 0) dt = ts[i] - ts[i - 1];
        g_dtT[t * NB + b] = fmaxf(dt, 1e-6f);
    }
    if (i < NG * NH * GB) { g_h0x[i] = 0.f; g_h1x[i] = 0.f; }   // h(-1) = 0
    if (blockIdx.x < 64) {
        const int kq = blockIdx.x, o = tid;
        const int k0 = kq * 4;
        const int rank = o >> 5, ol = o & 31;
        const int idx = (rank * 64 + kq) * 32 + ol;
        { const float* p = gh_w0 + o * NH + k0;
          g_WA0[idx] = make_float4(p[0], p[1], p[2], p[3]); }
        { const float* p = bb_w0 + o * (NS + NH) + NS + k0;
          g_WA1[idx] = make_float4(p[0], p[1], p[2], p[3]); }
        { const float* p = gh_w1 + o * NH + k0;
          g_WH0[idx] = make_float4(p[0], p[1], p[2], p[3]); }
        { const float* p = bb_w1 + o * (2 * NH) + NH + k0;
          g_WH1[idx] = make_float4(p[0], p[1], p[2], p[3]); }
        { const float* p = gx_w1 + o * NH + k0;
          g_WX1g[idx] = make_float4(p[0], p[1], p[2], p[3]); }
        { const float* p = bb_w1 + o * (2 * NH) + k0;
          g_WX1b[idx] = make_float4(p[0], p[1], p[2], p[3]); }
        if (kq < 8)
            g_wx0[(rank * 8 + kq) * 32 + ol] =
                make_float2(gx_w0[o * NS + kq], bb_w0[o * (NS + NH) + kq]);
        if (kq == 0) {
            g_bias[0 * NH + o] = gx_b0[o] + gb0[o];
            g_bias[1 * NH + o] = bb_b0[o];
            g_bias[2 * NH + o] = log1pf(expf(lt0[o]));
            g_bias[3 * NH + o] = gx_b1[o] + gb1[o];
            g_bias[4 * NH + o] = bb_b1[o];
            g_bias[5 * NH + o] = log1pf(expf(lt1[o]));
        }
    }
    if (blockIdx.x == 64 && tid < NG) g_bar[tid] = 0u;
}

// ---------------------------------------------------------------------------
__device__ __forceinline__ void ffma2(ull& acc, ull a, ull b) {
    asm("fma.rn.f32x2 %0, %1, %2, %0;" : "+l"(acc) : "l"(a), "l"(b));
}
__device__ __forceinline__ void add2(ull& a, ull b) {
    asm("add.rn.f32x2 %0, %0, %1;" : "+l"(a) : "l"(b));
}
__device__ __forceinline__ ull splat2(float v) {
    ull r; asm("mov.b64 %0, {%1,%1};" : "=l"(r) : "f"(v)); return r;
}
__device__ __forceinline__ void unpack2(ull v, float& lo, float& hi) {
    asm("mov.b64 {%0,%1}, %2;" : "=f"(lo), "=f"(hi) : "l"(v));
}
__device__ __forceinline__ float fast_tanh(float x) {
    float y; asm("tanh.approx.f32 %0, %1;" : "=f"(y) : "f"(x)); return y;
}
__device__ __forceinline__ float cfc_one(float ag, float af, float sp, float dt, float hold) {
    const float g = __fdividef(1.f, 1.f + __expf(-ag));
    const float f = fast_tanh(af);
    const float d = __expf(-dt * (sp + fabsf(g)));
    return d * hold + (1.f - d) * f;
}
__device__ __forceinline__ unsigned ld_acq(const unsigned* p) {
    unsigned v;
    asm volatile("ld.acquire.gpu.global.u32 %0, [%1];" : "=r"(v) : "l"(p) : "memory");
    return v;
}
__device__ __forceinline__ void red_release(unsigned* p) {
    asm volatile("red.add.release.gpu.global.u32 [%0], %1;" :: "l"(p), "r"(1u) : "memory");
}
__device__ __forceinline__ void bar_arrive(int id) {
    asm volatile("bar.arrive %0, %1;" :: "r"(id), "r"(NTHR) : "memory");
}
__device__ __forceinline__ void bar_sync_n(int id) {
    asm volatile("bar.sync %0, %1;" :: "r"(id), "r"(NTHR) : "memory");
}

// one k-column MAC: splat weights, 8 batch-pair FFMA2 per stream
#define ACCK(WGC, WBC, HBASE, KIDX) do {                                      \
    const ull sg_ = splat2(WGC);                                              \
    const ull sb_ = splat2(WBC);                                              \
    const ulonglong2* hr_ = (const ulonglong2*)((HBASE) + (KIDX) * GB);       \
    const ulonglong2 p0_ = hr_[0], p1_ = hr_[1], p2_ = hr_[2], p3_ = hr_[3];  \
    ffma2(ag[0], sg_, p0_.x); ffma2(af[0], sb_, p0_.x);                       \
    ffma2(ag[1], sg_, p0_.y); ffma2(af[1], sb_, p0_.y);                       \
    ffma2(ag[2], sg_, p1_.x); ffma2(af[2], sb_, p1_.x);                       \
    ffma2(ag[3], sg_, p1_.y); ffma2(af[3], sb_, p1_.y);                       \
    ffma2(ag[4], sg_, p2_.x); ffma2(af[4], sb_, p2_.x);                       \
    ffma2(ag[5], sg_, p2_.y); ffma2(af[5], sb_, p2_.y);                       \
    ffma2(ag[6], sg_, p3_.x); ffma2(af[6], sb_, p3_.x);                       \
    ffma2(ag[7], sg_, p3_.y); ffma2(af[7], sb_, p3_.y);                       \
} while (0)

// SMEM byte offsets
#define OFF_WA0 0
#define OFF_WA1 32768
#define OFF_WH0 65536
#define OFF_WH1 98304
#define OFF_H0  131072        // [2][256][16] f32 = 32768 (double-buffered)
#define OFF_H1  163840        // [256][16] f32 = 16384
#define OFF_RED 180224        // [8][8][32] ulonglong2 = 32768
#define OFF_XN  212992        // [2][8][16] f32 = 1024 (double-buffered)
#define OFF_DT  214016        // [2][16] f32 = 128
#define OFF_LAT 214144        // 256
#define OFF_LN  214400        // 64
#define SMEM_BYTES 214464

__global__ void __launch_bounds__(NTHR, 1)
liquid_main_kernel(
    const float* __restrict__ xs,
    const float* __restrict__ ln_g, const float* __restrict__ ln_b,
    const float* __restrict__ lp_w, const float* __restrict__ lp_b,
    const float* __restrict__ r1_w, const float* __restrict__ r1_b,
    const float* __restrict__ r2_w, const float* __restrict__ r2_b,
    float* __restrict__ out)
{
    extern __shared__ char smem[];
    const float4* WA0 = (const float4*)(smem + OFF_WA0);
    const float4* WA1 = (const float4*)(smem + OFF_WA1);
    const float4* WH0 = (const float4*)(smem + OFF_WH0);
    const float4* WH1 = (const float4*)(smem + OFF_WH1);
    float* h0s  = (float*)(smem + OFF_H0);        // [buf][k][b]
    float* h1s  = (float*)(smem + OFF_H1);        // [k][b]
    ulonglong2* red = (ulonglong2*)(smem + OFF_RED);   // [bp][ws][ol]
    float* xn_s = (float*)(smem + OFF_XN);        // [buf][k][b]
    float* dt_s = (float*)(smem + OFF_DT);        // [buf][b]
    float* lat_s = (float*)(smem + OFF_LAT);
    float* ln_s = (float*)(smem + OFF_LN);        // [0..7]=gamma, [8..15]=beta

    const int tid  = threadIdx.x;
    const int ol   = tid & 31;
    const int ws   = tid >> 5;          // k-segment / epi batch-pair
    const int lane = ol;
    const int rank = blockIdx.x & 7;
    const int grp  = blockIdx.x >> 3;
    const int og   = rank * 32 + ol;
    const int batch0 = grp * GB;

    // ---- load resident weight slices into SMEM (coalesced) ----
    {
        const float4* s0 = g_WA0 + rank * 2048;  float4* d0 = (float4*)(smem + OFF_WA0);
        const float4* s1 = g_WA1 + rank * 2048;  float4* d1 = (float4*)(smem + OFF_WA1);
        const float4* s2 = g_WH0 + rank * 2048;  float4* d2 = (float4*)(smem + OFF_WH0);
        const float4* s3 = g_WH1 + rank * 2048;  float4* d3 = (float4*)(smem + OFF_WH1);
        for (int i = tid; i < 2048; i += NTHR) {
            d0[i] = s0[i]; d1[i] = s1[i]; d2[i] = s2[i]; d3[i] = s3[i];
        }
    }
    // zero h buffers + LN params
    {
        float4* z0 = (float4*)h0s; float4* z1 = (float4*)h1s;
        const float4 zz = make_float4(0.f, 0.f, 0.f, 0.f);
        for (int i = tid; i < 2048; i += NTHR) z0[i] = zz;   // both h0 bufs
        for (int i = tid; i < 1024; i += NTHR) z1[i] = zz;
        if (tid < NS) { ln_s[tid] = ln_g[tid]; ln_s[8 + tid] = ln_b[tid]; }
    }

    // persistent register weights: cell1 x-part (this thread's 8 kq)
    float4 wx1g_q[8], wx1b_q[8];
    #pragma unroll
    for (int j = 0; j < 8; j++) {
        wx1g_q[j] = g_WX1g[(rank * 64 + ws * 8 + j) * 32 + ol];
        wx1b_q[j] = g_WX1b[(rank * 64 + ws * 8 + j) * 32 + ol];
    }
    // cell0 x-part (k = ws only), pre-splatted
    ull wx0g2, wx0b2;
    {
        const float2 w = g_wx0[(rank * 8 + ws) * 32 + ol];
        wx0g2 = splat2(w.x); wx0b2 = splat2(w.y);
    }
    // biases for epilogue role
    const float bg0 = g_bias[0 * NH + og];
    const float bf0 = g_bias[1 * NH + og];
    const float sp0 = g_bias[2 * NH + og];
    const float bg1 = g_bias[3 * NH + og];
    const float bf1 = g_bias[4 * NH + og];
    const float sp1 = g_bias[5 * NH + og];

    // ---- initial xn(0)/dt(0) into buf 0, prefetch x(1)/dt(1) ----
    float4 px0, px1; float pdt = 1.f;
    if (tid < GB) {
        const float4* xp = (const float4*)(xs + (size_t)(batch0 + tid) * NT * NS);
        float4 a = xp[0], c = xp[1];
        float x[NS] = {a.x, a.y, a.z, a.w, c.x, c.y, c.z, c.w};
        float mu = 0.f;
        #pragma unroll
        for (int k = 0; k < NS; k++) mu += x[k];
        mu *= 0.125f;
        float var = 0.f;
        #pragma unroll
        for (int k = 0; k < NS; k++) { float d = x[k] - mu; var += d * d; }
        var *= 0.125f;
        const float inv = rsqrtf(var + 1e-5f);
        #pragma unroll
        for (int k = 0; k < NS; k++)
            xn_s[k * GB + tid] = (x[k] - mu) * inv * ln_g[k] + ln_b[k];
        dt_s[tid] = g_dtT[0 * NB + batch0 + tid];
        px0 = xp[2]; px1 = xp[3];          // x(1)
        pdt = g_dtT[1 * NB + batch0 + tid];
    }
    __syncthreads();

    const float4* h1src = (const float4*)(g_h1x + (size_t)grp * NH * GB) + ws * 128;
    const float4* h0src = (const float4*)(g_h0x + (size_t)grp * NH * GB) + ws * 128;
    float4* h1dst = (float4*)h1s + ws * 128;

    for (int t = 0; t < NT; t++) {
        const int bA = t & 1;
        float* h0old = h0s + bA * 4096;
        float* h0new = h0s + (bA ^ 1) * 4096;
        const float* xnc = xn_s + bA * 128;
        const float* dtc = dt_s + bA * GB;

        // ---- LN(t+1) into buf bA^1 (no sync; consumed next step) ----
        if (tid < GB) {
            float x[NS] = {px0.x, px0.y, px0.z, px0.w, px1.x, px1.y, px1.z, px1.w};
            float mu = 0.f;
            #pragma unroll
            for (int k = 0; k < NS; k++) mu += x[k];
            mu *= 0.125f;
            float var = 0.f;
            #pragma unroll
            for (int k = 0; k < NS; k++) { float d = x[k] - mu; var += d * d; }
            var *= 0.125f;
            const float inv = rsqrtf(var + 1e-5f);
            float* xnn = xn_s + (bA ^ 1) * 128;
            #pragma unroll
            for (int k = 0; k < NS; k++)
                xnn[k * GB + tid] = (x[k] - mu) * inv * ln_s[k] + ln_s[8 + k];
            dt_s[(bA ^ 1) * GB + tid] = pdt;
            const int tt = (t + 2 < NT) ? t + 2 : NT - 1;
            const float4* xp = (const float4*)(xs + ((size_t)(batch0 + tid) * NT + tt) * NS);
            px0 = xp[0]; px1 = xp[1];
            pdt = g_dtT[tt * NB + batch0 + tid];
        }

        // =================== stage A: CfC cell 0 (h0old = h0(t-1)) =================
        ull ag[8], af[8];
        #pragma unroll
        for (int bp = 0; bp < 8; bp++) { ag[bp] = 0ull; af[bp] = 0ull; }
        {   // x-part: warp ws handles sensor k = ws
            const ulonglong2* xr = (const ulonglong2*)(xnc + ws * GB);
            const ulonglong2 q0 = xr[0], q1 = xr[1], q2 = xr[2], q3 = xr[3];
            ffma2(ag[0], wx0g2, q0.x); ffma2(af[0], wx0b2, q0.x);
            ffma2(ag[1], wx0g2, q0.y); ffma2(af[1], wx0b2, q0.y);
            ffma2(ag[2], wx0g2, q1.x); ffma2(af[2], wx0b2, q1.x);
            ffma2(ag[3], wx0g2, q1.y); ffma2(af[3], wx0b2, q1.y);
            ffma2(ag[4], wx0g2, q2.x); ffma2(af[4], wx0b2, q2.x);
            ffma2(ag[5], wx0g2, q2.y); ffma2(af[5], wx0b2, q2.y);
            ffma2(ag[6], wx0g2, q3.x); ffma2(af[6], wx0b2, q3.x);
            ffma2(ag[7], wx0g2, q3.y); ffma2(af[7], wx0b2, q3.y);
        }
        #pragma unroll 4
        for (int kq = 0; kq < 8; kq++) {
            const int kqg = ws * 8 + kq;
            const float4 wg4 = WA0[kqg * 32 + ol];
            const float4 wb4 = WA1[kqg * 32 + ol];
            const int k0 = kqg * 4;
            ACCK(wg4.x, wb4.x, h0old, k0 + 0);
            ACCK(wg4.y, wb4.y, h0old, k0 + 1);
            ACCK(wg4.z, wb4.z, h0old, k0 + 2);
            ACCK(wg4.w, wb4.w, h0old, k0 + 3);
        }

        // ---- per-warp: wait bar1(t-1) + reload own h1 seg ----
        if (lane == 0) {
            const unsigned tgt = 16u * (unsigned)t;
            while (ld_acq(&g_bar[grp]) < tgt) {}
        }
        __syncwarp();
        {
            h1dst[lane]       = __ldcg(h1src + lane);
            h1dst[lane + 32]  = __ldcg(h1src + lane + 32);
            h1dst[lane + 64]  = __ldcg(h1src + lane + 64);
            h1dst[lane + 96]  = __ldcg(h1src + lane + 96);
        }
        __syncwarp();

        #pragma unroll
        for (int bp = 0; bp < 8; bp++)
            red[(bp * 8 + ws) * 32 + ol] = make_ulonglong2(ag[bp], af[bp]);
        __syncthreads();   // S2
        {   // epilogue A: (output og, batch-pair bp = ws); hold from h0old
            const int bp = ws;
            ull g2 = 0ull, f2 = 0ull;
            #pragma unroll
            for (int w2 = 0; w2 < 8; w2++) {
                const ulonglong2 v = red[(bp * 8 + w2) * 32 + ol];
                add2(g2, v.x); add2(f2, v.y);
            }
            float gA, gB, fA, fB, hA, hB;
            unpack2(g2, gA, gB); unpack2(f2, fA, fB);
            const ull holdp = *(const ull*)(h0old + og * GB + 2 * bp);
            unpack2(holdp, hA, hB);
            const float hnA = cfc_one(gA + bg0, fA + bf0, sp0, dtc[2 * bp + 0], hA);
            const float hnB = cfc_one(gB + bg0, fB + bf0, sp0, dtc[2 * bp + 1], hB);
            *(float2*)(g_h0x + ((size_t)grp * NH + og) * GB + 2 * bp) = make_float2(hnA, hnB);
        }
        // ---- S3 asymmetric: warps 1-7 arrive & continue; warp 0 syncs + releases --
        if (ws != 0) {
            bar_arrive(1);
        } else {
            bar_sync_n(1);
            if (lane == 0) red_release(&g_bar[grp]);   // arrive bar0(t)
        }

        // ============ stage B part 1a: h-contribution (h1s = h1(t-1)), kq 0..5 =====
        #pragma unroll
        for (int bp = 0; bp < 8; bp++) { ag[bp] = 0ull; af[bp] = 0ull; }
        #pragma unroll
        for (int kq = 0; kq < 6; kq++) {
            const int kqg = ws * 8 + kq;
            const float4 wg4 = WH0[kqg * 32 + ol];
            const float4 wb4 = WH1[kqg * 32 + ol];
            const int k0 = kqg * 4;
            ACCK(wg4.x, wb4.x, h1s, k0 + 0);
            ACCK(wg4.y, wb4.y, h1s, k0 + 1);
            ACCK(wg4.z, wb4.z, h1s, k0 + 2);
            ACCK(wg4.w, wb4.w, h1s, k0 + 3);
        }
        // ---- per-warp: wait bar0(t), LDG own h0 seg to regs (hidden by B1b) ----
        if (lane == 0) {
            const unsigned tgt = 16u * (unsigned)t + 8u;
            while (ld_acq(&g_bar[grp]) < tgt) {}
        }
        __syncwarp();
        float4 r0 = __ldcg(h0src + lane);
        float4 r1 = __ldcg(h0src + lane + 32);
        float4 r2 = __ldcg(h0src + lane + 64);
        float4 r3 = __ldcg(h0src + lane + 96);
        // ============ stage B part 1b: kq 6..7 (covers the LDG latency) ============
        #pragma unroll
        for (int kq = 6; kq < 8; kq++) {
            const int kqg = ws * 8 + kq;
            const float4 wg4 = WH0[kqg * 32 + ol];
            const float4 wb4 = WH1[kqg * 32 + ol];
            const int k0 = kqg * 4;
            ACCK(wg4.x, wb4.x, h1s, k0 + 0);
            ACCK(wg4.y, wb4.y, h1s, k0 + 1);
            ACCK(wg4.z, wb4.z, h1s, k0 + 2);
            ACCK(wg4.w, wb4.w, h1s, k0 + 3);
        }
        {   // store reloaded h0(t) into buf bA^1 (own segment)
            float4* d = (float4*)h0new + ws * 128;
            d[lane] = r0; d[lane + 32] = r1; d[lane + 64] = r2; d[lane + 96] = r3;
        }
        __syncwarp();

        // ============ stage B part 2: x-contribution (h0new, register weights) =====
        #pragma unroll
        for (int j = 0; j < 8; j++) {
            const float4 wg4 = wx1g_q[j];
            const float4 wb4 = wx1b_q[j];
            const int k0 = (ws * 8 + j) * 4;
            ACCK(wg4.x, wb4.x, h0new, k0 + 0);
            ACCK(wg4.y, wb4.y, h0new, k0 + 1);
            ACCK(wg4.z, wb4.z, h0new, k0 + 2);
            ACCK(wg4.w, wb4.w, h0new, k0 + 3);
        }
        #pragma unroll
        for (int bp = 0; bp < 8; bp++)
            red[(bp * 8 + ws) * 32 + ol] = make_ulonglong2(ag[bp], af[bp]);
        __syncthreads();   // S8
        {   // epilogue B: hold from h1s (= h1(t-1))
            const int bp = ws;
            ull g2 = 0ull, f2 = 0ull;
            #pragma unroll
            for (int w2 = 0; w2 < 8; w2++) {
                const ulonglong2 v = red[(bp * 8 + w2) * 32 + ol];
                add2(g2, v.x); add2(f2, v.y);
            }
            float gA, gB, fA, fB, hA, hB;
            unpack2(g2, gA, gB); unpack2(f2, fA, fB);
            const ull holdp = *(const ull*)(h1s + og * GB + 2 * bp);
            unpack2(holdp, hA, hB);
            const float hnA = cfc_one(gA + bg1, fA + bf1, sp1, dtc[2 * bp + 0], hA);
            const float hnB = cfc_one(gB + bg1, fB + bf1, sp1, dtc[2 * bp + 1], hB);
            *(float2*)(g_h1x + ((size_t)grp * NH + og) * GB + 2 * bp) = make_float2(hnA, hnB);
        }
        // ---- S9 asymmetric: warps 0-6 arrive & continue; warp 7 syncs + releases --
        if (ws != 7) {
            bar_arrive(2);
        } else {
            bar_sync_n(2);
            if (lane == 0) red_release(&g_bar[grp]);   // arrive bar1(t)
        }
        // NOTE: h1s WAR for next step's reload is safe: the reload warp first
        // spins on bar1(t) (released only after S9 sync saw all epilogue reads
        // of h1s complete across the group, incl. this CTA's own warps).
    }

    // ---- final: per-warp wait last bar1, reload own h1 seg, join, head ----
    if (lane == 0) {
        const unsigned tgt = 16u * (unsigned)NT;
        while (ld_acq(&g_bar[grp]) < tgt) {}
    }
    __syncwarp();
    {
        h1dst[lane]       = __ldcg(h1src + lane);
        h1dst[lane + 32]  = __ldcg(h1src + lane + 32);
        h1dst[lane + 64]  = __ldcg(h1src + lane + 64);
        h1dst[lane + 96]  = __ldcg(h1src + lane + 96);
    }
    __syncthreads();

    // =================== head: latent + risk (2 batches per CTA) ===================
    if (tid < 64) {
        const int i = tid >> 5, l = tid & 31;
        const int lb = rank * 2 + i;
        const int gb = batch0 + lb;
        const float* wrow = lp_w + l * NH;
        float acc = lp_b[l];
        for (int k = 0; k < NH; k++) acc = fmaf(h1s[k * GB + lb], __ldg(wrow + k), acc);
        const float latv = tanhf(acc);
        lat_s[i * 32 + l] = latv;
        out[(size_t)gb * 32 + l] = latv;
    }
    __syncthreads();
    if (tid < 64) {
        const int i = tid >> 5, j = tid & 31;
        const int gb = batch0 + rank * 2 + i;
        const float* wrow = r1_w + j * 32;
        float acc = r1_b[j];
        #pragma unroll
        for (int k = 0; k < 32; k++) acc = fmaf(lat_s[i * 32 + k], __ldg(wrow + k), acc);
        const float hid = 0.5f * acc * (1.f + erff(acc * 0.70710678118654752f));
        float v = hid * __ldg(r2_w + j);
        #pragma unroll
        for (int off = 16; off; off >>= 1) v += __shfl_xor_sync(0xffffffffu, v, off);
        if (j == 0) {
            const float risk = 1.f / (1.f + __expf(-(v + r2_b[0])));
            out[NB * 32 + gb] = risk;
        }
    }
}

// ---------------------------------------------------------------------------
extern "C" void kernel_launch(void* const* d_in, const int* in_sizes, int n_in,
                              void* d_out, int out_size) {
    const float* xs    = (const float*)d_in[0];
    const float* ts    = (const float*)d_in[1];
    const float* ln_g  = (const float*)d_in[2];
    const float* ln_b  = (const float*)d_in[3];
    const float* bb_w0 = (const float*)d_in[4];
    const float* bb_b0 = (const float*)d_in[5];
    const float* gx_w0 = (const float*)d_in[6];
    const float* gx_b0 = (const float*)d_in[7];
    const float* gh_w0 = (const float*)d_in[8];
    const float* gb0   = (const float*)d_in[9];
    const float* lt0   = (const float*)d_in[10];
    const float* bb_w1 = (const float*)d_in[11];
    const float* bb_b1 = (const float*)d_in[12];
    const float* gx_w1 = (const float*)d_in[13];
    const float* gx_b1 = (const float*)d_in[14];
    const float* gh_w1 = (const float*)d_in[15];
    const float* gb1   = (const float*)d_in[16];
    const float* lt1   = (const float*)d_in[17];
    const float* lp_w  = (const float*)d_in[18];
    const float* lp_b  = (const float*)d_in[19];
    const float* r1_w  = (const float*)d_in[20];
    const float* r1_b  = (const float*)d_in[21];
    const float* r2_w  = (const float*)d_in[22];
    const float* r2_b  = (const float*)d_in[23];
    float* out = (float*)d_out;

    cudaFuncSetAttribute(liquid_main_kernel,
                         cudaFuncAttributeMaxDynamicSharedMemorySize, SMEM_BYTES);

    prep_kernel<<<1024, 256>>>(ts, bb_w0, gx_w0, gx_b0, gh_w0, gb0, lt0,
                               bb_w1, gx_w1, gx_b1, gh_w1, gb1, lt1,
                               bb_b0, bb_b1);
    liquid_main_kernel<<<NCTA, NTHR, SMEM_BYTES>>>(
        xs, ln_g, ln_b, lp_w, lp_b, r1_w, r1_b, r2_w, r2_b, out);
}